// round 7
// baseline (speedup 1.0000x reference)
#include <cuda_runtime.h>
#include <cstdint>

#define TT 2048
#define BB 64
#define HH 128
#define GG 384
#define MTOT (BB * TT)   // 131072
#define NC 32            // pipeline chunks
#define TCH (TT / NC)    // 64 steps per chunk
#define SMEMG ((64 * 128 + 128 * 128) * 4)

// Scratch (device globals: no runtime allocation allowed)
__device__ float g_gx[(size_t)3 * MTOT * GG];   // per-layer pre-activations
__device__ float g_buf[(size_t)3 * MTOT * HH];  // per-layer outputs
__device__ float g_h[3 * BB * HH];              // chunk-boundary hidden state

// ---------- packed f32x2 helpers (sm_100+ PTX) ----------
__device__ __forceinline__ unsigned long long pk2(float x, float y) {
    unsigned long long r;
    asm("mov.b64 %0, {%1, %2};" : "=l"(r) : "f"(x), "f"(y));
    return r;
}
__device__ __forceinline__ void upk2(unsigned long long v, float& x, float& y) {
    asm("mov.b64 {%0, %1}, %2;" : "=f"(x), "=f"(y) : "l"(v));
}
__device__ __forceinline__ unsigned long long ffma2(unsigned long long a,
                                                    unsigned long long b,
                                                    unsigned long long c) {
    unsigned long long d;
    asm("fma.rn.f32x2 %0, %1, %2, %3;" : "=l"(d) : "l"(a), "l"(b), "l"(c));
    return d;
}
__device__ __forceinline__ float sigm(float x) {
    return 1.0f / (1.0f + __expf(-x));
}
// cp.async 16B gmem->smem (LDGSTS): no register staging.
__device__ __forceinline__ void cp16(uint32_t saddr, const void* g) {
    asm volatile("cp.async.cg.shared.global [%0], [%1], 16;"
                 :: "r"(saddr), "l"(g));
}
__device__ __forceinline__ void cp_commit() {
    asm volatile("cp.async.commit_group;");
}
__device__ __forceinline__ void cp_wait0() {
    asm volatile("cp.async.wait_group 0;");
}

// ============================================================================
// Chunked persistent GRU scan: TWO batch rows per CTA (rows 2b, 2b+1).
// 32 CTAs/scan -> 96 CTAs across 3 concurrently-pipelined layers: fits 148
// SMs with no stragglers (each scan CTA needs the whole SM's register file).
// Thread c<256: z/r gate column c (both rows); c>=256: h column (both rows).
// Weights (128 regs/thread) are shared across the two rows; the second row
// adds an independent FMA/LDS stream that fills issue-stall slack.
// gx staged 4 steps at a time via cp.async double buffer (no reg prefetch).
// ============================================================================
__global__ void __launch_bounds__(GG, 1) gru_scan(
    const float* __restrict__ gx,    // [B, T, 384]
    const float* __restrict__ rec,   // [128, 384]
    const float* __restrict__ brec,  // [384]
    float* __restrict__ out,         // [B, T, 128]
    float* __restrict__ hstate,      // [B, 128]
    int t0)
{
    __shared__ __align__(16) float h0[HH], h1[HH];
    __shared__ float szr0[2 * HH], szr1[2 * HH];
    __shared__ __align__(16) float sb0[2][4 * GG];  // row0 gx stage (2 x 6KB)
    __shared__ __align__(16) float sb1[2][4 * GG];  // row1 gx stage

    const int b0 = blockIdx.x * 2;
    const int b1 = b0 + 1;
    const int c = threadIdx.x;
    const bool is_h = (c >= 2 * HH);

    unsigned long long w2[64];
#pragma unroll
    for (int p = 0; p < 64; ++p)
        w2[p] = pk2(rec[(2 * p) * GG + c], rec[(2 * p + 1) * GG + c]);
    const float brc = brec[c];

    float hr0 = 0.0f, hr1 = 0.0f;
    if (is_h) {
        const int cc = c - 2 * HH;
        if (t0 != 0) {
            hr0 = hstate[b0 * HH + cc];
            hr1 = hstate[b1 * HH + cc];
        }
        h0[cc] = hr0;
        h1[cc] = hr1;
    }

    const float* gxp0 = gx + (size_t)b0 * TT * GG;
    const float* gxp1 = gx + (size_t)b1 * TT * GG;
    float* outp0 = out + (size_t)b0 * TT * HH;
    float* outp1 = out + (size_t)b1 * TT * HH;

    const uint32_t sa0 = (uint32_t)__cvta_generic_to_shared(sb0);
    const uint32_t sa1 = (uint32_t)__cvta_generic_to_shared(sb1);

    // Prologue: stage group 0 (4 steps x 1536B per row; thread c copies 16B).
    cp16(sa0 + c * 16, gxp0 + (size_t)t0 * GG + c * 4);
    cp16(sa1 + c * 16, gxp1 + (size_t)t0 * GG + c * 4);
    cp_commit();
    cp_wait0();
    __syncthreads();

    const int tend = t0 + TCH;
    int cur = 0;
    for (int tg = t0; tg < tend; tg += 4) {
        const bool hp = (tg + 4) < tend;
        if (hp) {
            uint32_t dst = (cur ^ 1) * (4 * GG * 4) + c * 16;
            cp16(sa0 + dst, gxp0 + (size_t)(tg + 4) * GG + c * 4);
            cp16(sa1 + dst, gxp1 + (size_t)(tg + 4) * GG + c * 4);
            cp_commit();
        }

#pragma unroll
        for (int k = 0; k < 4; ++k) {
            // Dual GEMV: 4 independent f32x2 chains (2 per row).
            unsigned long long A0 = pk2(brc, 0.0f), A1 = 0ull;
            unsigned long long B0 = pk2(brc, 0.0f), B1 = 0ull;
            const ulonglong2* H0 = (const ulonglong2*)h0;
            const ulonglong2* H1 = (const ulonglong2*)h1;
#pragma unroll
            for (int j = 0; j < 32; ++j) {
                ulonglong2 v0 = H0[j];
                ulonglong2 v1 = H1[j];
                A0 = ffma2(v0.x, w2[2 * j], A0);
                A1 = ffma2(v0.y, w2[2 * j + 1], A1);
                B0 = ffma2(v1.x, w2[2 * j], B0);
                B1 = ffma2(v1.y, w2[2 * j + 1], B1);
            }
            float ax, ay, bx, by, cx, cy, dx, dy;
            upk2(A0, ax, ay); upk2(A1, bx, by);
            upk2(B0, cx, cy); upk2(B1, dx, dy);
            const float a0 = (ax + bx) + (ay + by);
            const float a1 = (cx + dx) + (cy + dy);

            const float gxv0 = sb0[cur][k * GG + c];
            const float gxv1 = sb1[cur][k * GG + c];

            if (!is_h) {
                szr0[c] = sigm(a0 + gxv0);
                szr1[c] = sigm(a1 + gxv1);
            }
            if (k == 3) cp_wait0();
            __syncthreads();

            if (is_h) {
                const int cc = c - 2 * HH;
                float z0 = szr0[cc], r0 = szr0[cc + HH];
                float z1 = szr1[cc], r1 = szr1[cc + HH];
                float p0 = gxv0 + r0 * a0;
                float p1 = gxv1 + r1 * a1;
                float c0 = 2.0f * sigm(2.0f * p0) - 1.0f;  // tanh
                float c1 = 2.0f * sigm(2.0f * p1) - 1.0f;
                float hn0 = fmaf(z0, hr0 - c0, c0);
                float hn1 = fmaf(z1, hr1 - c1, c1);
                hr0 = hn0; hr1 = hn1;
                h0[cc] = hn0; h1[cc] = hn1;
                outp0[(size_t)(tg + k) * HH + cc] = hn0;
                outp1[(size_t)(tg + k) * HH + cc] = hn1;
            }
            __syncthreads();
        }
        cur ^= 1;
    }

    if (is_h) {
        const int cc = c - 2 * HH;
        hstate[b0 * HH + cc] = hr0;
        hstate[b1 * HH + cc] = hr1;
    }
}

// ============================================================================
// fp32 GEMM + bias (+ optional sigmoid), packed f32x2 FMA.
// Chunked: rows (b, t), t in [t0, t0+TCH). TCH=64 -> one 64-row tile per b.
// ============================================================================
__global__ void __launch_bounds__(256, 2) gemm_bias(
    const float* __restrict__ A, const float* __restrict__ Bm,
    const float* __restrict__ bias, float* __restrict__ C,
    int N, int do_sig, int t0)
{
    extern __shared__ float smem[];
    float* As = smem;            // [64][128]
    float* Bs = smem + 64 * 128; // [128][128]

    const int tid = threadIdx.x;
    const int m0 = blockIdx.x * TT + t0;
    const int n0 = blockIdx.y * 128;

    const float4* A4 = (const float4*)(A + (size_t)m0 * 128);
    float4* As4 = (float4*)As;
#pragma unroll
    for (int i = 0; i < 8; ++i) {
        int idx = i * 256 + tid;
        As4[idx] = A4[idx];
    }
    const int N4 = N >> 2;
    const float4* B4 = (const float4*)Bm;
    float4* Bs4 = (float4*)Bs;
#pragma unroll
    for (int i = 0; i < 16; ++i) {
        int idx = i * 256 + tid;
        int k = idx >> 5;
        int c4 = idx & 31;
        Bs4[idx] = B4[(size_t)k * N4 + (n0 >> 2) + c4];
    }
    __syncthreads();

    const int rg = tid >> 4;
    const int cg = tid & 15;

    unsigned long long acc[2][4][2];
#pragma unroll
    for (int hf = 0; hf < 2; ++hf)
#pragma unroll
        for (int i = 0; i < 4; ++i) {
            acc[hf][i][0] = 0ull;
            acc[hf][i][1] = 0ull;
        }

    const ulonglong2* BsU = (const ulonglong2*)Bs;

#pragma unroll 8
    for (int k = 0; k < 128; ++k) {
        ulonglong2 bv0 = BsU[k * 32 + cg];
        ulonglong2 bv1 = BsU[k * 32 + 16 + cg];
        float a0 = As[(rg * 4 + 0) * 128 + k];
        float a1 = As[(rg * 4 + 1) * 128 + k];
        float a2 = As[(rg * 4 + 2) * 128 + k];
        float a3 = As[(rg * 4 + 3) * 128 + k];
        unsigned long long aa0 = pk2(a0, a0);
        unsigned long long aa1 = pk2(a1, a1);
        unsigned long long aa2 = pk2(a2, a2);
        unsigned long long aa3 = pk2(a3, a3);

        acc[0][0][0] = ffma2(aa0, bv0.x, acc[0][0][0]);
        acc[0][0][1] = ffma2(aa0, bv0.y, acc[0][0][1]);
        acc[0][1][0] = ffma2(aa1, bv0.x, acc[0][1][0]);
        acc[0][1][1] = ffma2(aa1, bv0.y, acc[0][1][1]);
        acc[0][2][0] = ffma2(aa2, bv0.x, acc[0][2][0]);
        acc[0][2][1] = ffma2(aa2, bv0.y, acc[0][2][1]);
        acc[0][3][0] = ffma2(aa3, bv0.x, acc[0][3][0]);
        acc[0][3][1] = ffma2(aa3, bv0.y, acc[0][3][1]);
        acc[1][0][0] = ffma2(aa0, bv1.x, acc[1][0][0]);
        acc[1][0][1] = ffma2(aa0, bv1.y, acc[1][0][1]);
        acc[1][1][0] = ffma2(aa1, bv1.x, acc[1][1][0]);
        acc[1][1][1] = ffma2(aa1, bv1.y, acc[1][1][1]);
        acc[1][2][0] = ffma2(aa2, bv1.x, acc[1][2][0]);
        acc[1][2][1] = ffma2(aa2, bv1.y, acc[1][2][1]);
        acc[1][3][0] = ffma2(aa3, bv1.x, acc[1][3][0]);
        acc[1][3][1] = ffma2(aa3, bv1.y, acc[1][3][1]);
    }

#pragma unroll
    for (int hf = 0; hf < 2; ++hf) {
        int col = n0 + hf * 64 + cg * 4;
        float4 bb = *(const float4*)(bias + col);
#pragma unroll
        for (int i = 0; i < 4; ++i) {
            float4 v;
            upk2(acc[hf][i][0], v.x, v.y);
            upk2(acc[hf][i][1], v.z, v.w);
            v.x += bb.x; v.y += bb.y; v.z += bb.z; v.w += bb.w;
            if (do_sig) {
                v.x = sigm(v.x); v.y = sigm(v.y);
                v.z = sigm(v.z); v.w = sigm(v.w);
            }
            *(float4*)(C + (size_t)(m0 + rg * 4 + i) * N + col) = v;
        }
    }
}

// ============================================================================
// Streams + events (created once at load; host objects only, no device mem).
// s[0..2]=scan (HIGH priority), s[3..5]=per-layer gemm, s[6]=out-projection.
// ============================================================================
struct PipeRes {
    cudaStream_t s[7];
    cudaEvent_t fork;
    cudaEvent_t eg[3][NC];   // gemm(l, i) done
    cudaEvent_t es[3][NC];   // scan(l, i) done
    cudaEvent_t tail[7];
    PipeRes() {
        int lo, hi;
        cudaDeviceGetStreamPriorityRange(&lo, &hi);
        for (int i = 0; i < 3; ++i)
            cudaStreamCreateWithPriority(&s[i], cudaStreamNonBlocking, hi);
        for (int i = 3; i < 7; ++i)
            cudaStreamCreateWithPriority(&s[i], cudaStreamNonBlocking, lo);
        cudaEventCreateWithFlags(&fork, cudaEventDisableTiming);
        for (int l = 0; l < 3; ++l)
            for (int i = 0; i < NC; ++i) {
                cudaEventCreateWithFlags(&eg[l][i], cudaEventDisableTiming);
                cudaEventCreateWithFlags(&es[l][i], cudaEventDisableTiming);
            }
        for (int i = 0; i < 7; ++i)
            cudaEventCreateWithFlags(&tail[i], cudaEventDisableTiming);
    }
};
static PipeRes P;

extern "C" void kernel_launch(void* const* d_in, const int* in_sizes, int n_in,
                              void* d_out, int out_size)
{
    const float* X    = (const float*)d_in[0];  // [64,2048,128]
    const float* Wk   = (const float*)d_in[1];  // [128,384]
    const float* Wr   = (const float*)d_in[2];  // [128,384]
    const float* bin  = (const float*)d_in[3];  // [384]
    const float* brec = (const float*)d_in[4];  // [384]
    const float* Wo   = (const float*)d_in[5];  // [128,128]
    const float* bo   = (const float*)d_in[6];  // [128]
    float* out = (float*)d_out;                 // [64,2048,128]

    float *gx, *buf, *hst;
    cudaGetSymbolAddress((void**)&gx,  g_gx);
    cudaGetSymbolAddress((void**)&buf, g_buf);
    cudaGetSymbolAddress((void**)&hst, g_h);

    cudaFuncSetAttribute(gemm_bias, cudaFuncAttributeMaxDynamicSharedMemorySize,
                         SMEMG);

    // Fork capture into worker streams.
    cudaEventRecord(P.fork, 0);
    for (int i = 0; i < 7; ++i) cudaStreamWaitEvent(P.s[i], P.fork, 0);

    const dim3 gg(BB, GG / 128);  // 64 x 3
    const dim3 go(BB, HH / 128);  // 64 x 1

    // Interleaved enqueue, chunk-major. Gemm throttled to 2-chunk lookahead.
    for (int i = 0; i < NC; ++i) {
        for (int l = 0; l < 3; ++l) {
            const float* Ain = (l == 0) ? X : (buf + (size_t)(l - 1) * MTOT * HH);
            float* gxl  = gx  + (size_t)l * MTOT * GG;
            float* bufl = buf + (size_t)l * MTOT * HH;
            float* hl   = hst + (size_t)l * BB * HH;
            cudaStream_t sg = P.s[3 + l];
            cudaStream_t sc = P.s[l];

            if (l > 0) cudaStreamWaitEvent(sg, P.es[l - 1][i], 0);
            if (i >= 2) cudaStreamWaitEvent(sg, P.es[l][i - 2], 0);
            gemm_bias<<<gg, 256, SMEMG, sg>>>(Ain, Wk, bin, gxl, GG, 0, i * TCH);
            cudaEventRecord(P.eg[l][i], sg);

            cudaStreamWaitEvent(sc, P.eg[l][i], 0);
            gru_scan<<<BB / 2, GG, 0, sc>>>(gxl, Wr, brec, bufl, hl, i * TCH);
            cudaEventRecord(P.es[l][i], sc);
        }
        cudaStreamWaitEvent(P.s[6], P.es[2][i], 0);
        gemm_bias<<<go, 256, SMEMG, P.s[6]>>>(buf + (size_t)2 * MTOT * HH,
                                              Wo, bo, out, HH, 1, i * TCH);
    }

    // Join everything back to the default (capturing) stream.
    for (int i = 0; i < 7; ++i) {
        cudaEventRecord(P.tail[i], P.s[i]);
        cudaStreamWaitEvent(0, P.tail[i], 0);
    }
}

// round 8
// speedup vs baseline: 1.0812x; 1.0812x over previous
#include <cuda_runtime.h>
#include <cstdint>

#define TT 2048
#define BB 64
#define HH 128
#define GG 384
#define MTOT (BB * TT)   // 131072
#define NC 32            // pipeline chunks
#define TCH (TT / NC)    // 64 steps per chunk
// tf32 gemm smem: A[64][132] f32 + Bhi[128][72] + Blo[128][72] (b32)
#define SMEMT (64 * 132 * 4 + 2 * 128 * 72 * 4)

// Scratch (device globals: no runtime allocation allowed)
__device__ float g_gx[(size_t)3 * MTOT * GG];   // per-layer pre-activations
__device__ float g_buf[(size_t)3 * MTOT * HH];  // per-layer outputs
__device__ float g_h[3 * BB * HH];              // chunk-boundary hidden state
__device__ uint32_t g_wkh[128 * GG];            // Wk tf32 hi
__device__ uint32_t g_wkl[128 * GG];            // Wk tf32 lo
__device__ uint32_t g_woh[128 * HH];            // Wo tf32 hi
__device__ uint32_t g_wol[128 * HH];            // Wo tf32 lo

// ---------- helpers ----------
__device__ __forceinline__ unsigned long long pk2(float x, float y) {
    unsigned long long r;
    asm("mov.b64 %0, {%1, %2};" : "=l"(r) : "f"(x), "f"(y));
    return r;
}
__device__ __forceinline__ void upk2(unsigned long long v, float& x, float& y) {
    asm("mov.b64 {%0, %1}, %2;" : "=f"(x), "=f"(y) : "l"(v));
}
__device__ __forceinline__ unsigned long long ffma2(unsigned long long a,
                                                    unsigned long long b,
                                                    unsigned long long c) {
    unsigned long long d;
    asm("fma.rn.f32x2 %0, %1, %2, %3;" : "=l"(d) : "l"(a), "l"(b), "l"(c));
    return d;
}
__device__ __forceinline__ float sigm(float x) {
    return 1.0f / (1.0f + __expf(-x));
}
__device__ __forceinline__ uint32_t f2tf(float x) {
    uint32_t r;
    asm("cvt.rna.tf32.f32 %0, %1;" : "=r"(r) : "f"(x));
    return r;
}
__device__ __forceinline__ void mma_tf32(float* c, uint32_t a0, uint32_t a1,
                                         uint32_t a2, uint32_t a3,
                                         uint32_t b0, uint32_t b1) {
    asm volatile(
        "mma.sync.aligned.m16n8k8.row.col.f32.tf32.tf32.f32 "
        "{%0,%1,%2,%3}, {%4,%5,%6,%7}, {%8,%9}, {%0,%1,%2,%3};"
        : "+f"(c[0]), "+f"(c[1]), "+f"(c[2]), "+f"(c[3])
        : "r"(a0), "r"(a1), "r"(a2), "r"(a3), "r"(b0), "r"(b1));
}

// ============================================================================
// Weight split: W -> (tf32 hi, tf32 lo) for 3xTF32 gemms. Run once per call.
// ============================================================================
__global__ void __launch_bounds__(256) split_w(const float* __restrict__ wk,
                                               const float* __restrict__ wo) {
    int i = blockIdx.x * 256 + threadIdx.x;
    if (i < 128 * GG) {
        float v = wk[i];
        uint32_t h = f2tf(v);
        g_wkh[i] = h;
        g_wkl[i] = f2tf(v - __uint_as_float(h));
    } else {
        int j = i - 128 * GG;
        if (j < 128 * HH) {
            float v = wo[j];
            uint32_t h = f2tf(v);
            g_woh[j] = h;
            g_wol[j] = f2tf(v - __uint_as_float(h));
        }
    }
}

// ============================================================================
// Chunked persistent GRU scan (R5-proven): one CTA/row, steps [t0,t0+TCH).
// ============================================================================
__global__ void __launch_bounds__(GG, 1) gru_scan(
    const float* __restrict__ gx, const float* __restrict__ rec,
    const float* __restrict__ brec, float* __restrict__ out,
    float* __restrict__ hstate, int t0)
{
    __shared__ __align__(16) float h[HH];
    __shared__ float szr[2 * HH];
    __shared__ __align__(16) float sbuf[2][4 * GG];

    const int b = blockIdx.x;
    const int c = threadIdx.x;
    const bool is_h = (c >= 2 * HH);

    unsigned long long w2[64];
#pragma unroll
    for (int p = 0; p < 64; ++p)
        w2[p] = pk2(rec[(2 * p) * GG + c], rec[(2 * p + 1) * GG + c]);
    const float brc = brec[c];

    float hreg = 0.0f;
    if (is_h) {
        const int cc = c - 2 * HH;
        hreg = (t0 == 0) ? 0.0f : hstate[b * HH + cc];
        h[cc] = hreg;
    }

    const float4* gx4b = (const float4*)(gx + (size_t)b * TT * GG);
    ((float4*)sbuf[0])[c] = gx4b[(size_t)t0 * 96 + c];
    float* outp = out + (size_t)b * TT * HH;
    __syncthreads();

    const int tend = t0 + TCH;
    int cur = 0;
    for (int tg = t0; tg < tend; tg += 4) {
        float4 pf;
        const bool havepf = (tg + 4) < tend;
        if (havepf) pf = gx4b[(size_t)(tg + 4) * 96 + c];

#pragma unroll
        for (int k = 0; k < 4; ++k) {
            unsigned long long a0 = pk2(brc, 0.0f);
            unsigned long long a1 = 0ull, a2 = 0ull, a3 = 0ull;
            const ulonglong2* h4 = (const ulonglong2*)h;
#pragma unroll
            for (int j = 0; j < 16; ++j) {
                ulonglong2 p = h4[2 * j];
                ulonglong2 q = h4[2 * j + 1];
                a0 = ffma2(p.x, w2[4 * j + 0], a0);
                a1 = ffma2(p.y, w2[4 * j + 1], a1);
                a2 = ffma2(q.x, w2[4 * j + 2], a2);
                a3 = ffma2(q.y, w2[4 * j + 3], a3);
            }
            float x0, y0, x1, y1, x2, y2, x3, y3;
            upk2(a0, x0, y0); upk2(a1, x1, y1);
            upk2(a2, x2, y2); upk2(a3, x3, y3);
            float a = ((x0 + x1) + (x2 + x3)) + ((y0 + y1) + (y2 + y3));

            const float gxv = sbuf[cur][k * GG + c];
            if (!is_h) szr[c] = sigm(a + gxv);
            __syncthreads();

            if (is_h) {
                const int cc = c - 2 * HH;
                float z = szr[cc];
                float r = szr[cc + HH];
                float pre = gxv + r * a;
                float cand = 2.0f * sigm(2.0f * pre) - 1.0f;  // tanh
                float hn = fmaf(z, hreg - cand, cand);
                hreg = hn;
                h[cc] = hn;
                outp[(size_t)(tg + k) * HH + cc] = hn;
            }
            if (k == 3 && havepf) ((float4*)sbuf[cur ^ 1])[c] = pf;
            __syncthreads();
        }
        cur ^= 1;
    }

    if (is_h) hstate[b * HH + (c - 2 * HH)] = hreg;
}

// ============================================================================
// 3xTF32 tensor-core GEMM + bias (+ optional sigmoid).
// C[64, Ntile=64] per block: C = A[64,128] @ W[128,N] slice.
// W pre-split into tf32 hi/lo (global). A split on the fly.
// 8 warps: warp w -> m-strip (w&3)*16, n-half (w>>2)*32 (4 n8-subtiles).
// Padded smem (A:132, B:72) -> conflict-free fragment LDS.
// ============================================================================
__global__ void __launch_bounds__(256, 2) gemm_tf32(
    const float* __restrict__ A, const uint32_t* __restrict__ Bh,
    const uint32_t* __restrict__ Bl, const float* __restrict__ bias,
    float* __restrict__ C, int N, int do_sig, int t0)
{
    extern __shared__ float smem[];
    float* As = smem;                                  // [64][132]
    uint32_t* Bsh = (uint32_t*)(smem + 64 * 132);      // [128][72]
    uint32_t* Bsl = Bsh + 128 * 72;                    // [128][72]

    const int tid = threadIdx.x;
    const int m0 = blockIdx.x * TT + t0;
    const int n0 = blockIdx.y * 64;

    // Stage A (64x128, contiguous since lda==128)
    const float4* A4 = (const float4*)(A + (size_t)m0 * 128);
#pragma unroll
    for (int i = 0; i < 8; ++i) {
        int idx = i * 256 + tid;       // 0..2047
        int r = idx >> 5, c4 = idx & 31;
        *(float4*)(As + r * 132 + c4 * 4) = A4[idx];
    }
    // Stage B hi/lo (128 x 64 cols at n0)
    const int N4 = N >> 2;
    const uint4* Bh4 = (const uint4*)Bh;
    const uint4* Bl4 = (const uint4*)Bl;
#pragma unroll
    for (int i = 0; i < 8; ++i) {
        int idx = i * 256 + tid;       // 0..2047
        int k = idx >> 4, c4 = idx & 15;
        *(uint4*)(Bsh + k * 72 + c4 * 4) = Bh4[(size_t)k * N4 + (n0 >> 2) + c4];
        *(uint4*)(Bsl + k * 72 + c4 * 4) = Bl4[(size_t)k * N4 + (n0 >> 2) + c4];
    }
    __syncthreads();

    const int lane = tid & 31, wid = tid >> 5;
    const int g = lane >> 2, t = lane & 3;
    const int ms = (wid & 3) * 16;
    const int nh = (wid >> 2) * 32;

    float acc[4][4];
#pragma unroll
    for (int s = 0; s < 4; ++s)
#pragma unroll
        for (int q = 0; q < 4; ++q) acc[s][q] = 0.0f;

#pragma unroll
    for (int ks = 0; ks < 16; ++ks) {
        const int k0 = ks * 8;
        float a0f = As[(ms + g) * 132 + k0 + t];
        float a1f = As[(ms + g + 8) * 132 + k0 + t];
        float a2f = As[(ms + g) * 132 + k0 + t + 4];
        float a3f = As[(ms + g + 8) * 132 + k0 + t + 4];
        uint32_t ah0 = f2tf(a0f), ah1 = f2tf(a1f);
        uint32_t ah2 = f2tf(a2f), ah3 = f2tf(a3f);
        uint32_t al0 = f2tf(a0f - __uint_as_float(ah0));
        uint32_t al1 = f2tf(a1f - __uint_as_float(ah1));
        uint32_t al2 = f2tf(a2f - __uint_as_float(ah2));
        uint32_t al3 = f2tf(a3f - __uint_as_float(ah3));
#pragma unroll
        for (int s = 0; s < 4; ++s) {
            const int bcol = nh + s * 8 + g;
            uint32_t bh0 = Bsh[(k0 + t) * 72 + bcol];
            uint32_t bh1 = Bsh[(k0 + t + 4) * 72 + bcol];
            uint32_t bl0 = Bsl[(k0 + t) * 72 + bcol];
            uint32_t bl1 = Bsl[(k0 + t + 4) * 72 + bcol];
            mma_tf32(acc[s], ah0, ah1, ah2, ah3, bh0, bh1);
            mma_tf32(acc[s], al0, al1, al2, al3, bh0, bh1);
            mma_tf32(acc[s], ah0, ah1, ah2, ah3, bl0, bl1);
        }
    }

#pragma unroll
    for (int s = 0; s < 4; ++s) {
        const int col = n0 + nh + s * 8 + 2 * t;
        const float b0v = bias[col], b1v = bias[col + 1];
        float2 v0 = make_float2(acc[s][0] + b0v, acc[s][1] + b1v);
        float2 v1 = make_float2(acc[s][2] + b0v, acc[s][3] + b1v);
        if (do_sig) {
            v0.x = sigm(v0.x); v0.y = sigm(v0.y);
            v1.x = sigm(v1.x); v1.y = sigm(v1.y);
        }
        *(float2*)(C + (size_t)(m0 + ms + g) * N + col) = v0;
        *(float2*)(C + (size_t)(m0 + ms + g + 8) * N + col) = v1;
    }
}

// ============================================================================
// Streams + events (host objects only, created once).
// ============================================================================
struct PipeRes {
    cudaStream_t s[7];
    cudaEvent_t fork;
    cudaEvent_t eg[3][NC];
    cudaEvent_t es[3][NC];
    cudaEvent_t tail[7];
    PipeRes() {
        int lo, hi;
        cudaDeviceGetStreamPriorityRange(&lo, &hi);
        for (int i = 0; i < 3; ++i)
            cudaStreamCreateWithPriority(&s[i], cudaStreamNonBlocking, hi);
        for (int i = 3; i < 7; ++i)
            cudaStreamCreateWithPriority(&s[i], cudaStreamNonBlocking, lo);
        cudaEventCreateWithFlags(&fork, cudaEventDisableTiming);
        for (int l = 0; l < 3; ++l)
            for (int i = 0; i < NC; ++i) {
                cudaEventCreateWithFlags(&eg[l][i], cudaEventDisableTiming);
                cudaEventCreateWithFlags(&es[l][i], cudaEventDisableTiming);
            }
        for (int i = 0; i < 7; ++i)
            cudaEventCreateWithFlags(&tail[i], cudaEventDisableTiming);
    }
};
static PipeRes P;

extern "C" void kernel_launch(void* const* d_in, const int* in_sizes, int n_in,
                              void* d_out, int out_size)
{
    const float* X    = (const float*)d_in[0];
    const float* Wk   = (const float*)d_in[1];
    const float* Wr   = (const float*)d_in[2];
    const float* bin  = (const float*)d_in[3];
    const float* brec = (const float*)d_in[4];
    const float* Wo   = (const float*)d_in[5];
    const float* bo   = (const float*)d_in[6];
    float* out = (float*)d_out;

    float *gx, *buf, *hst;
    uint32_t *wkh, *wkl, *woh, *wol;
    cudaGetSymbolAddress((void**)&gx,  g_gx);
    cudaGetSymbolAddress((void**)&buf, g_buf);
    cudaGetSymbolAddress((void**)&hst, g_h);
    cudaGetSymbolAddress((void**)&wkh, g_wkh);
    cudaGetSymbolAddress((void**)&wkl, g_wkl);
    cudaGetSymbolAddress((void**)&woh, g_woh);
    cudaGetSymbolAddress((void**)&wol, g_wol);

    cudaFuncSetAttribute(gemm_tf32, cudaFuncAttributeMaxDynamicSharedMemorySize,
                         SMEMT);

    // Weight split on default stream BEFORE the fork (ordered for all workers).
    split_w<<<(128 * GG + 128 * HH + 255) / 256, 256>>>(Wk, Wo);

    cudaEventRecord(P.fork, 0);
    for (int i = 0; i < 7; ++i) cudaStreamWaitEvent(P.s[i], P.fork, 0);

    const dim3 gg(BB, GG / 64);  // 64 x 6
    const dim3 go(BB, HH / 64);  // 64 x 2

    for (int i = 0; i < NC; ++i) {
        for (int l = 0; l < 3; ++l) {
            const float* Ain = (l == 0) ? X : (buf + (size_t)(l - 1) * MTOT * HH);
            float* gxl  = gx  + (size_t)l * MTOT * GG;
            float* bufl = buf + (size_t)l * MTOT * HH;
            float* hl   = hst + (size_t)l * BB * HH;
            cudaStream_t sg = P.s[3 + l];
            cudaStream_t sc = P.s[l];

            if (l > 0) cudaStreamWaitEvent(sg, P.es[l - 1][i], 0);
            if (i >= 2) cudaStreamWaitEvent(sg, P.es[l][i - 2], 0);
            gemm_tf32<<<gg, 256, SMEMT, sg>>>(Ain, wkh, wkl, bin, gxl, GG, 0,
                                              i * TCH);
            cudaEventRecord(P.eg[l][i], sg);

            cudaStreamWaitEvent(sc, P.eg[l][i], 0);
            gru_scan<<<BB, GG, 0, sc>>>(gxl, Wr, brec, bufl, hl, i * TCH);
            cudaEventRecord(P.es[l][i], sc);
        }
        cudaStreamWaitEvent(P.s[6], P.es[2][i], 0);
        gemm_tf32<<<go, 256, SMEMT, P.s[6]>>>(buf + (size_t)2 * MTOT * HH,
                                              woh, wol, bo, out, HH, 1,
                                              i * TCH);
    }

    for (int i = 0; i < 7; ++i) {
        cudaEventRecord(P.tail[i], P.s[i]);
        cudaStreamWaitEvent(0, P.tail[i], 0);
    }
}

// round 9
// speedup vs baseline: 1.1914x; 1.1019x over previous
#include <cuda_runtime.h>
#include <cstdint>

#define TT 2048
#define BB 64
#define HH 128
#define GG 384
#define MTOT (BB * TT)   // 131072
#define NC 16            // pipeline chunks
#define TCH (TT / NC)    // 128 steps per chunk
// tf32 gemm smem: A[64][132] f32 + Bhi[128][72] (b32)
#define SMEMT (64 * 132 * 4 + 128 * 72 * 4)

// Scratch (device globals: no runtime allocation allowed)
__device__ float g_gx[(size_t)3 * MTOT * GG];   // per-layer pre-activations
__device__ float g_buf[(size_t)3 * MTOT * HH];  // per-layer outputs
__device__ float g_h[3 * BB * HH];              // chunk-boundary hidden state
__device__ uint32_t g_wkh[128 * GG];            // Wk tf32 (rounded)
__device__ uint32_t g_woh[128 * HH];            // Wo tf32 (rounded)

// ---------- helpers ----------
__device__ __forceinline__ unsigned long long pk2(float x, float y) {
    unsigned long long r;
    asm("mov.b64 %0, {%1, %2};" : "=l"(r) : "f"(x), "f"(y));
    return r;
}
__device__ __forceinline__ void upk2(unsigned long long v, float& x, float& y) {
    asm("mov.b64 {%0, %1}, %2;" : "=f"(x), "=f"(y) : "l"(v));
}
__device__ __forceinline__ unsigned long long ffma2(unsigned long long a,
                                                    unsigned long long b,
                                                    unsigned long long c) {
    unsigned long long d;
    asm("fma.rn.f32x2 %0, %1, %2, %3;" : "=l"(d) : "l"(a), "l"(b), "l"(c));
    return d;
}
__device__ __forceinline__ float sigm(float x) {
    return 1.0f / (1.0f + __expf(-x));
}
__device__ __forceinline__ uint32_t f2tf(float x) {
    uint32_t r;
    asm("cvt.rna.tf32.f32 %0, %1;" : "=r"(r) : "f"(x));
    return r;
}
__device__ __forceinline__ void mma_tf32(float* c, uint32_t a0, uint32_t a1,
                                         uint32_t a2, uint32_t a3,
                                         uint32_t b0, uint32_t b1) {
    asm volatile(
        "mma.sync.aligned.m16n8k8.row.col.f32.tf32.tf32.f32 "
        "{%0,%1,%2,%3}, {%4,%5,%6,%7}, {%8,%9}, {%0,%1,%2,%3};"
        : "+f"(c[0]), "+f"(c[1]), "+f"(c[2]), "+f"(c[3])
        : "r"(a0), "r"(a1), "r"(a2), "r"(a3), "r"(b0), "r"(b1));
}

// ============================================================================
// Weight rounding: W -> tf32 (hi only; 2-term scheme corrects A, not W).
// ============================================================================
__global__ void __launch_bounds__(256) split_w(const float* __restrict__ wk,
                                               const float* __restrict__ wo) {
    int i = blockIdx.x * 256 + threadIdx.x;
    if (i < 128 * GG) {
        g_wkh[i] = f2tf(wk[i]);
    } else {
        int j = i - 128 * GG;
        if (j < 128 * HH) g_woh[j] = f2tf(wo[j]);
    }
}

// ============================================================================
// Chunked persistent GRU scan (R5-proven): one CTA/row, steps [t0,t0+TCH).
// ============================================================================
__global__ void __launch_bounds__(GG, 1) gru_scan(
    const float* __restrict__ gx, const float* __restrict__ rec,
    const float* __restrict__ brec, float* __restrict__ out,
    float* __restrict__ hstate, int t0)
{
    __shared__ __align__(16) float h[HH];
    __shared__ float szr[2 * HH];
    __shared__ __align__(16) float sbuf[2][4 * GG];

    const int b = blockIdx.x;
    const int c = threadIdx.x;
    const bool is_h = (c >= 2 * HH);

    unsigned long long w2[64];
#pragma unroll
    for (int p = 0; p < 64; ++p)
        w2[p] = pk2(rec[(2 * p) * GG + c], rec[(2 * p + 1) * GG + c]);
    const float brc = brec[c];

    float hreg = 0.0f;
    if (is_h) {
        const int cc = c - 2 * HH;
        hreg = (t0 == 0) ? 0.0f : hstate[b * HH + cc];
        h[cc] = hreg;
    }

    const float4* gx4b = (const float4*)(gx + (size_t)b * TT * GG);
    ((float4*)sbuf[0])[c] = gx4b[(size_t)t0 * 96 + c];
    float* outp = out + (size_t)b * TT * HH;
    __syncthreads();

    const int tend = t0 + TCH;
    int cur = 0;
    for (int tg = t0; tg < tend; tg += 4) {
        float4 pf;
        const bool havepf = (tg + 4) < tend;
        if (havepf) pf = gx4b[(size_t)(tg + 4) * 96 + c];

#pragma unroll
        for (int k = 0; k < 4; ++k) {
            unsigned long long a0 = pk2(brc, 0.0f);
            unsigned long long a1 = 0ull, a2 = 0ull, a3 = 0ull;
            const ulonglong2* h4 = (const ulonglong2*)h;
#pragma unroll
            for (int j = 0; j < 16; ++j) {
                ulonglong2 p = h4[2 * j];
                ulonglong2 q = h4[2 * j + 1];
                a0 = ffma2(p.x, w2[4 * j + 0], a0);
                a1 = ffma2(p.y, w2[4 * j + 1], a1);
                a2 = ffma2(q.x, w2[4 * j + 2], a2);
                a3 = ffma2(q.y, w2[4 * j + 3], a3);
            }
            float x0, y0, x1, y1, x2, y2, x3, y3;
            upk2(a0, x0, y0); upk2(a1, x1, y1);
            upk2(a2, x2, y2); upk2(a3, x3, y3);
            float a = ((x0 + x1) + (x2 + x3)) + ((y0 + y1) + (y2 + y3));

            const float gxv = sbuf[cur][k * GG + c];
            if (!is_h) szr[c] = sigm(a + gxv);
            __syncthreads();

            if (is_h) {
                const int cc = c - 2 * HH;
                float z = szr[cc];
                float r = szr[cc + HH];
                float pre = gxv + r * a;
                float cand = 2.0f * sigm(2.0f * pre) - 1.0f;  // tanh
                float hn = fmaf(z, hreg - cand, cand);
                hreg = hn;
                h[cc] = hn;
                outp[(size_t)(tg + k) * HH + cc] = hn;
            }
            if (k == 3 && havepf) ((float4*)sbuf[cur ^ 1])[c] = pf;
            __syncthreads();
        }
        cur ^= 1;
    }

    if (is_h) hstate[b * HH + (c - 2 * HH)] = hreg;
}

// ============================================================================
// 2-term TF32 tensor-core GEMM + bias (+ optional sigmoid).
// C[64, 64] per block: C = A[64,128] @ W[128,N] slice, W pre-rounded to tf32.
// A split into hi/lo on the fly: C ~= ah@wh + al@wh (A error corrected,
// W carries one tf32 rounding -> ~1e-4 rel err, well under 1e-3 gate).
// ============================================================================
__global__ void __launch_bounds__(256, 2) gemm_tf32(
    const float* __restrict__ A, const uint32_t* __restrict__ Bh,
    const float* __restrict__ bias, float* __restrict__ C,
    int N, int do_sig, int t0)
{
    extern __shared__ float smem[];
    float* As = smem;                                  // [64][132]
    uint32_t* Bsh = (uint32_t*)(smem + 64 * 132);      // [128][72]

    const int tid = threadIdx.x;
    const int nb = blockIdx.x;
    const int m0 = (nb >> 1) * TT + t0 + (nb & 1) * 64;
    const int n0 = blockIdx.y * 64;

    // Stage A (64x128, contiguous since lda==128)
    const float4* A4 = (const float4*)(A + (size_t)m0 * 128);
#pragma unroll
    for (int i = 0; i < 8; ++i) {
        int idx = i * 256 + tid;       // 0..2047
        int r = idx >> 5, c4 = idx & 31;
        *(float4*)(As + r * 132 + c4 * 4) = A4[idx];
    }
    // Stage B hi (128 x 64 cols at n0)
    const int N4 = N >> 2;
    const uint4* Bh4 = (const uint4*)Bh;
#pragma unroll
    for (int i = 0; i < 8; ++i) {
        int idx = i * 256 + tid;       // 0..2047
        int k = idx >> 4, c4 = idx & 15;
        *(uint4*)(Bsh + k * 72 + c4 * 4) = Bh4[(size_t)k * N4 + (n0 >> 2) + c4];
    }
    __syncthreads();

    const int lane = tid & 31, wid = tid >> 5;
    const int g = lane >> 2, t = lane & 3;
    const int ms = (wid & 3) * 16;
    const int nh = (wid >> 2) * 32;

    float acc[4][4];
#pragma unroll
    for (int s = 0; s < 4; ++s)
#pragma unroll
        for (int q = 0; q < 4; ++q) acc[s][q] = 0.0f;

#pragma unroll
    for (int ks = 0; ks < 16; ++ks) {
        const int k0 = ks * 8;
        float a0f = As[(ms + g) * 132 + k0 + t];
        float a1f = As[(ms + g + 8) * 132 + k0 + t];
        float a2f = As[(ms + g) * 132 + k0 + t + 4];
        float a3f = As[(ms + g + 8) * 132 + k0 + t + 4];
        uint32_t ah0 = f2tf(a0f), ah1 = f2tf(a1f);
        uint32_t ah2 = f2tf(a2f), ah3 = f2tf(a3f);
        uint32_t al0 = f2tf(a0f - __uint_as_float(ah0));
        uint32_t al1 = f2tf(a1f - __uint_as_float(ah1));
        uint32_t al2 = f2tf(a2f - __uint_as_float(ah2));
        uint32_t al3 = f2tf(a3f - __uint_as_float(ah3));
#pragma unroll
        for (int s = 0; s < 4; ++s) {
            const int bcol = nh + s * 8 + g;
            uint32_t bh0 = Bsh[(k0 + t) * 72 + bcol];
            uint32_t bh1 = Bsh[(k0 + t + 4) * 72 + bcol];
            mma_tf32(acc[s], ah0, ah1, ah2, ah3, bh0, bh1);
            mma_tf32(acc[s], al0, al1, al2, al3, bh0, bh1);
        }
    }

#pragma unroll
    for (int s = 0; s < 4; ++s) {
        const int col = n0 + nh + s * 8 + 2 * t;
        const float b0v = bias[col], b1v = bias[col + 1];
        float2 v0 = make_float2(acc[s][0] + b0v, acc[s][1] + b1v);
        float2 v1 = make_float2(acc[s][2] + b0v, acc[s][3] + b1v);
        if (do_sig) {
            v0.x = sigm(v0.x); v0.y = sigm(v0.y);
            v1.x = sigm(v1.x); v1.y = sigm(v1.y);
        }
        *(float2*)(C + (size_t)(m0 + ms + g) * N + col) = v0;
        *(float2*)(C + (size_t)(m0 + ms + g + 8) * N + col) = v1;
    }
}

// ============================================================================
// Streams + events (host objects only, created once).
// ============================================================================
struct PipeRes {
    cudaStream_t s[7];
    cudaEvent_t fork;
    cudaEvent_t eg[3][NC];
    cudaEvent_t es[3][NC];
    cudaEvent_t tail[7];
    PipeRes() {
        int lo, hi;
        cudaDeviceGetStreamPriorityRange(&lo, &hi);
        for (int i = 0; i < 3; ++i)
            cudaStreamCreateWithPriority(&s[i], cudaStreamNonBlocking, hi);
        for (int i = 3; i < 7; ++i)
            cudaStreamCreateWithPriority(&s[i], cudaStreamNonBlocking, lo);
        cudaEventCreateWithFlags(&fork, cudaEventDisableTiming);
        for (int l = 0; l < 3; ++l)
            for (int i = 0; i < NC; ++i) {
                cudaEventCreateWithFlags(&eg[l][i], cudaEventDisableTiming);
                cudaEventCreateWithFlags(&es[l][i], cudaEventDisableTiming);
            }
        for (int i = 0; i < 7; ++i)
            cudaEventCreateWithFlags(&tail[i], cudaEventDisableTiming);
    }
};
static PipeRes P;

extern "C" void kernel_launch(void* const* d_in, const int* in_sizes, int n_in,
                              void* d_out, int out_size)
{
    const float* X    = (const float*)d_in[0];
    const float* Wk   = (const float*)d_in[1];
    const float* Wr   = (const float*)d_in[2];
    const float* bin  = (const float*)d_in[3];
    const float* brec = (const float*)d_in[4];
    const float* Wo   = (const float*)d_in[5];
    const float* bo   = (const float*)d_in[6];
    float* out = (float*)d_out;

    float *gx, *buf, *hst;
    uint32_t *wkh, *woh;
    cudaGetSymbolAddress((void**)&gx,  g_gx);
    cudaGetSymbolAddress((void**)&buf, g_buf);
    cudaGetSymbolAddress((void**)&hst, g_h);
    cudaGetSymbolAddress((void**)&wkh, g_wkh);
    cudaGetSymbolAddress((void**)&woh, g_woh);

    cudaFuncSetAttribute(gemm_tf32, cudaFuncAttributeMaxDynamicSharedMemorySize,
                         SMEMT);

    // Weight rounding on default stream BEFORE the fork.
    split_w<<<(128 * GG + 128 * HH + 255) / 256, 256>>>(Wk, Wo);

    cudaEventRecord(P.fork, 0);
    for (int i = 0; i < 7; ++i) cudaStreamWaitEvent(P.s[i], P.fork, 0);

    const dim3 gg(BB * 2, GG / 64);  // 128 x 6
    const dim3 go(BB * 2, HH / 64);  // 128 x 2

    for (int i = 0; i < NC; ++i) {
        for (int l = 0; l < 3; ++l) {
            const float* Ain = (l == 0) ? X : (buf + (size_t)(l - 1) * MTOT * HH);
            float* gxl  = gx  + (size_t)l * MTOT * GG;
            float* bufl = buf + (size_t)l * MTOT * HH;
            float* hl   = hst + (size_t)l * BB * HH;
            cudaStream_t sg = P.s[3 + l];
            cudaStream_t sc = P.s[l];

            if (l > 0) cudaStreamWaitEvent(sg, P.es[l - 1][i], 0);
            if (i >= 2) cudaStreamWaitEvent(sg, P.es[l][i - 2], 0);
            gemm_tf32<<<gg, 256, SMEMT, sg>>>(Ain, wkh, bin, gxl, GG, 0,
                                              i * TCH);
            cudaEventRecord(P.eg[l][i], sg);

            cudaStreamWaitEvent(sc, P.eg[l][i], 0);
            gru_scan<<<BB, GG, 0, sc>>>(gxl, Wr, brec, bufl, hl, i * TCH);
            cudaEventRecord(P.es[l][i], sc);
        }
        cudaStreamWaitEvent(P.s[6], P.es[2][i], 0);
        gemm_tf32<<<go, 256, SMEMT, P.s[6]>>>(buf + (size_t)2 * MTOT * HH,
                                              woh, bo, out, HH, 1,
                                              i * TCH);
    }

    for (int i = 0; i < 7; ++i) {
        cudaEventRecord(P.tail[i], P.s[i]);
        cudaStreamWaitEvent(0, P.tail[i], 0);
    }
}

// round 10
// speedup vs baseline: 1.2104x; 1.0160x over previous
#include <cuda_runtime.h>
#include <cuda_bf16.h>
#include <cstdint>

#define TT 2048
#define BB 64
#define HH 128
#define GG 384
#define MTOT (BB * TT)   // 131072
#define NC 16            // pipeline chunks
#define TCH (TT / NC)    // 128 steps per chunk
// bf16 gemm smem: AsH[64][68] + AsL[64][68] + Bs[64][72], all u32
#define SMEMB ((64 * 68 * 2 + 64 * 72) * 4)

// Scratch (device globals: no runtime allocation allowed)
__device__ float g_gx[(size_t)3 * MTOT * GG];       // per-layer pre-activations
__device__ float g_h[3 * BB * HH];                  // chunk-boundary hidden
__device__ unsigned short g_xhi[(size_t)MTOT * HH]; // X bf16 hi
__device__ unsigned short g_xlo[(size_t)MTOT * HH]; // X bf16 lo
__device__ unsigned short g_bhi[(size_t)3 * MTOT * HH]; // layer outputs hi
__device__ unsigned short g_blo[(size_t)3 * MTOT * HH]; // layer outputs lo
__device__ uint32_t g_wkpk[64 * GG];                // Wk bf16 k-pairs [kp][n]
__device__ uint32_t g_wopk[64 * HH];                // Wo bf16 k-pairs [kp][n]

// ---------- helpers ----------
__device__ __forceinline__ unsigned long long pk2(float x, float y) {
    unsigned long long r;
    asm("mov.b64 %0, {%1, %2};" : "=l"(r) : "f"(x), "f"(y));
    return r;
}
__device__ __forceinline__ void upk2(unsigned long long v, float& x, float& y) {
    asm("mov.b64 {%0, %1}, %2;" : "=f"(x), "=f"(y) : "l"(v));
}
__device__ __forceinline__ unsigned long long ffma2(unsigned long long a,
                                                    unsigned long long b,
                                                    unsigned long long c) {
    unsigned long long d;
    asm("fma.rn.f32x2 %0, %1, %2, %3;" : "=l"(d) : "l"(a), "l"(b), "l"(c));
    return d;
}
__device__ __forceinline__ float sigm(float x) {
    return 1.0f / (1.0f + __expf(-x));
}
__device__ __forceinline__ void mma_bf16(float* c, uint32_t a0, uint32_t a1,
                                         uint32_t a2, uint32_t a3,
                                         uint32_t b0, uint32_t b1) {
    asm volatile(
        "mma.sync.aligned.m16n8k16.row.col.f32.bf16.bf16.f32 "
        "{%0,%1,%2,%3}, {%4,%5,%6,%7}, {%8,%9}, {%0,%1,%2,%3};"
        : "+f"(c[0]), "+f"(c[1]), "+f"(c[2]), "+f"(c[3])
        : "r"(a0), "r"(a1), "r"(a2), "r"(a3), "r"(b0), "r"(b1));
}
__device__ __forceinline__ uint32_t packbf(float lo, float hi) {
    unsigned short l = __bfloat16_as_ushort(__float2bfloat16(lo));
    unsigned short h = __bfloat16_as_ushort(__float2bfloat16(hi));
    return (uint32_t)l | ((uint32_t)h << 16);
}

// ============================================================================
// Weight pack: W[128][N] fp32 -> [64][N] u32 of bf16 k-pairs (lo = even k).
// ============================================================================
__global__ void __launch_bounds__(256) pack_w(const float* __restrict__ wk,
                                              const float* __restrict__ wo) {
    int i = blockIdx.x * 256 + threadIdx.x;
    if (i < 64 * GG) {
        int kp = i / GG, n = i % GG;
        g_wkpk[kp * GG + n] = packbf(wk[(2 * kp) * GG + n],
                                     wk[(2 * kp + 1) * GG + n]);
    } else {
        int j = i - 64 * GG;
        if (j < 64 * HH) {
            int kp = j / HH, n = j % HH;
            g_wopk[kp * HH + n] = packbf(wo[(2 * kp) * HH + n],
                                         wo[(2 * kp + 1) * HH + n]);
        }
    }
}

// ============================================================================
// X split: fp32 -> bf16 hi + bf16 lo (residual), packed as u32 k-pairs.
// ============================================================================
__global__ void __launch_bounds__(256) split_x(const float* __restrict__ X) {
    size_t i = (size_t)blockIdx.x * 256 + threadIdx.x;
    if (i >= (size_t)MTOT * 64) return;
    float2 v = ((const float2*)X)[i];
    __nv_bfloat16 hx = __float2bfloat16(v.x);
    __nv_bfloat16 hy = __float2bfloat16(v.y);
    float rx = v.x - __bfloat162float(hx);
    float ry = v.y - __bfloat162float(hy);
    ((uint32_t*)g_xhi)[i] = (uint32_t)__bfloat16_as_ushort(hx) |
                            ((uint32_t)__bfloat16_as_ushort(hy) << 16);
    ((uint32_t*)g_xlo)[i] = packbf(rx, ry);
}

// ============================================================================
// Chunked persistent GRU scan (R5-proven GEMV/barrier structure).
// Output h emitted as bf16 hi+lo (consumed only by bf16 tensor gemms).
// ============================================================================
__global__ void __launch_bounds__(GG, 1) gru_scan(
    const float* __restrict__ gx, const float* __restrict__ rec,
    const float* __restrict__ brec, unsigned short* __restrict__ outhi,
    unsigned short* __restrict__ outlo, float* __restrict__ hstate, int t0)
{
    __shared__ __align__(16) float h[HH];
    __shared__ float szr[2 * HH];
    __shared__ __align__(16) float sbuf[2][4 * GG];

    const int b = blockIdx.x;
    const int c = threadIdx.x;
    const bool is_h = (c >= 2 * HH);

    unsigned long long w2[64];
#pragma unroll
    for (int p = 0; p < 64; ++p)
        w2[p] = pk2(rec[(2 * p) * GG + c], rec[(2 * p + 1) * GG + c]);
    const float brc = brec[c];

    float hreg = 0.0f;
    if (is_h) {
        const int cc = c - 2 * HH;
        hreg = (t0 == 0) ? 0.0f : hstate[b * HH + cc];
        h[cc] = hreg;
    }

    const float4* gx4b = (const float4*)(gx + (size_t)b * TT * GG);
    ((float4*)sbuf[0])[c] = gx4b[(size_t)t0 * 96 + c];
    unsigned short* ohp = outhi + (size_t)b * TT * HH;
    unsigned short* olp = outlo + (size_t)b * TT * HH;
    __syncthreads();

    const int tend = t0 + TCH;
    int cur = 0;
    for (int tg = t0; tg < tend; tg += 4) {
        float4 pf;
        const bool havepf = (tg + 4) < tend;
        if (havepf) pf = gx4b[(size_t)(tg + 4) * 96 + c];

#pragma unroll
        for (int k = 0; k < 4; ++k) {
            unsigned long long a0 = pk2(brc, 0.0f);
            unsigned long long a1 = 0ull, a2 = 0ull, a3 = 0ull;
            const ulonglong2* h4 = (const ulonglong2*)h;
#pragma unroll
            for (int j = 0; j < 16; ++j) {
                ulonglong2 p = h4[2 * j];
                ulonglong2 q = h4[2 * j + 1];
                a0 = ffma2(p.x, w2[4 * j + 0], a0);
                a1 = ffma2(p.y, w2[4 * j + 1], a1);
                a2 = ffma2(q.x, w2[4 * j + 2], a2);
                a3 = ffma2(q.y, w2[4 * j + 3], a3);
            }
            float x0, y0, x1, y1, x2, y2, x3, y3;
            upk2(a0, x0, y0); upk2(a1, x1, y1);
            upk2(a2, x2, y2); upk2(a3, x3, y3);
            float a = ((x0 + x1) + (x2 + x3)) + ((y0 + y1) + (y2 + y3));

            const float gxv = sbuf[cur][k * GG + c];
            if (!is_h) szr[c] = sigm(a + gxv);
            __syncthreads();

            if (is_h) {
                const int cc = c - 2 * HH;
                float z = szr[cc];
                float r = szr[cc + HH];
                float pre = gxv + r * a;
                float cand = 2.0f * sigm(2.0f * pre) - 1.0f;  // tanh
                float hn = fmaf(z, hreg - cand, cand);
                hreg = hn;
                h[cc] = hn;
                __nv_bfloat16 bh = __float2bfloat16(hn);
                float hif = __bfloat162float(bh);
                __nv_bfloat16 bl = __float2bfloat16(hn - hif);
                const size_t o = (size_t)(tg + k) * HH + cc;
                ohp[o] = __bfloat16_as_ushort(bh);
                olp[o] = __bfloat16_as_ushort(bl);
            }
            if (k == 3 && havepf) ((float4*)sbuf[cur ^ 1])[c] = pf;
            __syncthreads();
        }
        cur ^= 1;
    }

    if (is_h) hstate[b * HH + (c - 2 * HH)] = hreg;
}

// ============================================================================
// bf16 tensor-core GEMM + bias (+ optional sigmoid).
// C[64,64] = (Ahi + Alo)[64,128] @ W[128,N] slice; all operands pre-split,
// zero in-loop conversion. 2 mma per (k16, n8) subtile.
// ============================================================================
__global__ void __launch_bounds__(256, 2) gemm_bf16(
    const uint32_t* __restrict__ Ahi, const uint32_t* __restrict__ Alo,
    const uint32_t* __restrict__ Wpk, const float* __restrict__ bias,
    float* __restrict__ C, int N, int do_sig, int t0)
{
    extern __shared__ uint32_t sm[];
    uint32_t* AsH = sm;                 // [64][68]
    uint32_t* AsL = sm + 64 * 68;       // [64][68]
    uint32_t* Bs  = sm + 2 * 64 * 68;   // [64][72]

    const int tid = threadIdx.x;
    const int nb = blockIdx.x;
    const int m0 = (nb >> 1) * TT + t0 + (nb & 1) * 64;
    const int n0 = blockIdx.y * 64;

    // Stage A hi/lo: 64 rows x 64 u32 (k-pairs), 16 uint4 per row.
    const uint4* Ah4 = (const uint4*)(Ahi + (size_t)m0 * 64);
    const uint4* Al4 = (const uint4*)(Alo + (size_t)m0 * 64);
#pragma unroll
    for (int i = 0; i < 4; ++i) {
        int idx = i * 256 + tid;       // 0..1023
        int r = idx >> 4, c4 = idx & 15;
        *(uint4*)(AsH + r * 68 + c4 * 4) = Ah4[idx];
        *(uint4*)(AsL + r * 68 + c4 * 4) = Al4[idx];
    }
    // Stage W k-pairs: 64 kp x 64 cols at n0.
    const int N4 = N >> 2;
    const uint4* W4 = (const uint4*)Wpk;
#pragma unroll
    for (int i = 0; i < 4; ++i) {
        int idx = i * 256 + tid;       // 0..1023
        int kp = idx >> 4, c4 = idx & 15;
        *(uint4*)(Bs + kp * 72 + c4 * 4) = W4[(size_t)kp * N4 + (n0 >> 2) + c4];
    }
    __syncthreads();

    const int lane = tid & 31, wid = tid >> 5;
    const int g = lane >> 2, t = lane & 3;
    const int ms = (wid & 3) * 16;
    const int nh = (wid >> 2) * 32;

    float acc[4][4];
#pragma unroll
    for (int s = 0; s < 4; ++s)
#pragma unroll
        for (int q = 0; q < 4; ++q) acc[s][q] = 0.0f;

#pragma unroll
    for (int ks = 0; ks < 8; ++ks) {
        const int kp0 = ks * 8;        // 8 k-pairs = k16 per step
        uint32_t ah0 = AsH[(ms + g) * 68 + kp0 + t];
        uint32_t ah1 = AsH[(ms + g + 8) * 68 + kp0 + t];
        uint32_t ah2 = AsH[(ms + g) * 68 + kp0 + t + 4];
        uint32_t ah3 = AsH[(ms + g + 8) * 68 + kp0 + t + 4];
        uint32_t al0 = AsL[(ms + g) * 68 + kp0 + t];
        uint32_t al1 = AsL[(ms + g + 8) * 68 + kp0 + t];
        uint32_t al2 = AsL[(ms + g) * 68 + kp0 + t + 4];
        uint32_t al3 = AsL[(ms + g + 8) * 68 + kp0 + t + 4];
#pragma unroll
        for (int s = 0; s < 4; ++s) {
            const int bc = nh + s * 8 + g;
            uint32_t b0 = Bs[(kp0 + t) * 72 + bc];
            uint32_t b1 = Bs[(kp0 + t + 4) * 72 + bc];
            mma_bf16(acc[s], ah0, ah1, ah2, ah3, b0, b1);
            mma_bf16(acc[s], al0, al1, al2, al3, b0, b1);
        }
    }

#pragma unroll
    for (int s = 0; s < 4; ++s) {
        const int col = n0 + nh + s * 8 + 2 * t;
        const float b0v = bias[col], b1v = bias[col + 1];
        float2 v0 = make_float2(acc[s][0] + b0v, acc[s][1] + b1v);
        float2 v1 = make_float2(acc[s][2] + b0v, acc[s][3] + b1v);
        if (do_sig) {
            v0.x = sigm(v0.x); v0.y = sigm(v0.y);
            v1.x = sigm(v1.x); v1.y = sigm(v1.y);
        }
        *(float2*)(C + (size_t)(m0 + ms + g) * N + col) = v0;
        *(float2*)(C + (size_t)(m0 + ms + g + 8) * N + col) = v1;
    }
}

// ============================================================================
// Streams + events (host objects only, created once).
// ============================================================================
struct PipeRes {
    cudaStream_t s[7];
    cudaEvent_t fork;
    cudaEvent_t eg[3][NC];
    cudaEvent_t es[3][NC];
    cudaEvent_t tail[7];
    PipeRes() {
        int lo, hi;
        cudaDeviceGetStreamPriorityRange(&lo, &hi);
        for (int i = 0; i < 3; ++i)
            cudaStreamCreateWithPriority(&s[i], cudaStreamNonBlocking, hi);
        for (int i = 3; i < 7; ++i)
            cudaStreamCreateWithPriority(&s[i], cudaStreamNonBlocking, lo);
        cudaEventCreateWithFlags(&fork, cudaEventDisableTiming);
        for (int l = 0; l < 3; ++l)
            for (int i = 0; i < NC; ++i) {
                cudaEventCreateWithFlags(&eg[l][i], cudaEventDisableTiming);
                cudaEventCreateWithFlags(&es[l][i], cudaEventDisableTiming);
            }
        for (int i = 0; i < 7; ++i)
            cudaEventCreateWithFlags(&tail[i], cudaEventDisableTiming);
    }
};
static PipeRes P;

extern "C" void kernel_launch(void* const* d_in, const int* in_sizes, int n_in,
                              void* d_out, int out_size)
{
    const float* X    = (const float*)d_in[0];
    const float* Wk   = (const float*)d_in[1];
    const float* Wr   = (const float*)d_in[2];
    const float* bin  = (const float*)d_in[3];
    const float* brec = (const float*)d_in[4];
    const float* Wo   = (const float*)d_in[5];
    const float* bo   = (const float*)d_in[6];
    float* out = (float*)d_out;

    float *gx, *hst;
    unsigned short *xhi, *xlo, *bhi, *blo;
    uint32_t *wkpk, *wopk;
    cudaGetSymbolAddress((void**)&gx,   g_gx);
    cudaGetSymbolAddress((void**)&hst,  g_h);
    cudaGetSymbolAddress((void**)&xhi,  g_xhi);
    cudaGetSymbolAddress((void**)&xlo,  g_xlo);
    cudaGetSymbolAddress((void**)&bhi,  g_bhi);
    cudaGetSymbolAddress((void**)&blo,  g_blo);
    cudaGetSymbolAddress((void**)&wkpk, g_wkpk);
    cudaGetSymbolAddress((void**)&wopk, g_wopk);

    cudaFuncSetAttribute(gemm_bf16, cudaFuncAttributeMaxDynamicSharedMemorySize,
                         SMEMB);

    // Pre-fork: pack W, split X (ordered before all worker streams).
    pack_w<<<(64 * GG + 64 * HH + 255) / 256, 256>>>(Wk, Wo);
    split_x<<<(int)(((size_t)MTOT * 64 + 255) / 256), 256>>>(X);

    cudaEventRecord(P.fork, 0);
    for (int i = 0; i < 7; ++i) cudaStreamWaitEvent(P.s[i], P.fork, 0);

    const dim3 gg(BB * 2, GG / 64);  // 128 x 6
    const dim3 go(BB * 2, HH / 64);  // 128 x 2

    for (int i = 0; i < NC; ++i) {
        for (int l = 0; l < 3; ++l) {
            const uint32_t* Ah = (l == 0) ? (const uint32_t*)xhi
                : (const uint32_t*)(bhi) + (size_t)(l - 1) * MTOT * 64;
            const uint32_t* Al = (l == 0) ? (const uint32_t*)xlo
                : (const uint32_t*)(blo) + (size_t)(l - 1) * MTOT * 64;
            float* gxl = gx + (size_t)l * MTOT * GG;
            unsigned short* ohl = bhi + (size_t)l * MTOT * HH;
            unsigned short* oll = blo + (size_t)l * MTOT * HH;
            float* hl = hst + (size_t)l * BB * HH;
            cudaStream_t sg = P.s[3 + l];
            cudaStream_t sc = P.s[l];

            if (l > 0) cudaStreamWaitEvent(sg, P.es[l - 1][i], 0);
            if (i >= 2) cudaStreamWaitEvent(sg, P.es[l][i - 2], 0);
            gemm_bf16<<<gg, 256, SMEMB, sg>>>(Ah, Al, wkpk, bin, gxl, GG, 0,
                                              i * TCH);
            cudaEventRecord(P.eg[l][i], sg);

            cudaStreamWaitEvent(sc, P.eg[l][i], 0);
            gru_scan<<<BB, GG, 0, sc>>>(gxl, Wr, brec, ohl, oll, hl, i * TCH);
            cudaEventRecord(P.es[l][i], sc);
        }
        cudaStreamWaitEvent(P.s[6], P.es[2][i], 0);
        gemm_bf16<<<go, 256, SMEMB, P.s[6]>>>(
            (const uint32_t*)bhi + (size_t)2 * MTOT * 64,
            (const uint32_t*)blo + (size_t)2 * MTOT * 64,
            wopk, bo, out, HH, 1, i * TCH);
    }

    for (int i = 0; i < 7; ++i) {
        cudaEventRecord(P.tail[i], P.s[i]);
        cudaStreamWaitEvent(0, P.tail[i], 0);
    }
}